// round 3
// baseline (speedup 1.0000x reference)
#include <cuda_runtime.h>
#include <cuda_bf16.h>
#include <cstdint>
#include <cstdio>

#define NMAX 100000
#define EMAX 1600000
#define ETMAX (EMAX + NMAX)

// ---------------- scratch (device globals; no allocation allowed) ----------
__device__ __align__(256) float g_h1  [(size_t)NMAX * 128];  // layer1 h = x@W1
__device__ __align__(256) float g_agg1[(size_t)NMAX * 128];  // layer1 aggregated out
__device__ __align__(256) float g_h2  [(size_t)NMAX * 32];   // layer2 h
__device__ __align__(256) float g_ssrc1[NMAX * 4];
__device__ __align__(256) float g_sdst1[NMAX * 4];
__device__ __align__(256) float g_den1 [NMAX * 4];
__device__ __align__(256) float g_ssrc2[NMAX];
__device__ __align__(256) float g_sdst2[NMAX];
__device__ __align__(256) float g_den2 [NMAX];
__device__ __align__(256) float g_eexp[(size_t)ETMAX * 4];   // layer1: [E,4]; layer2 reuses [E,1]
__device__ __align__(256) int   g_src[ETMAX];
__device__ __align__(256) int   g_dst[ETMAX];
__device__ int g_is64;   // 1 if edge_index is int64, 0 if int32

// ---------------- helpers ---------------------------------------------------
__device__ __forceinline__ float lrelu(float v) { return v > 0.f ? v : 0.2f * v; }

__device__ __forceinline__ void red_add_v4(float* addr, float a, float b, float c, float d) {
    asm volatile("red.global.add.v4.f32 [%0], {%1,%2,%3,%4};"
                 :: "l"(addr), "f"(a), "f"(b), "f"(c), "f"(d) : "memory");
}

// ---------------- kernels ---------------------------------------------------

// Detect dtype of edge_index. If data is int64 with values < 2^31 (node ids),
// every odd 32-bit word is 0. For int32 data 64 consecutive odd words are
// essentially never all zero.
__global__ void k_detect_dtype(const int* __restrict__ ei32) {
    if (threadIdx.x == 0 && blockIdx.x == 0) {
        int all_zero = 1;
        for (int i = 0; i < 64; i++)
            if (ei32[2 * i + 1] != 0) { all_zero = 0; break; }
        g_is64 = all_zero;
    }
}

// edge_index (int32 or int64) -> int32 src/dst, self-loops appended, clamped.
__global__ void k_build_edges(const void* __restrict__ ei, int E, int N) {
    int i = blockIdx.x * blockDim.x + threadIdx.x;
    int etot = E + N;
    if (i >= etot) return;
    int s, d;
    if (i < E) {
        if (g_is64) {
            const long long* p = (const long long*)ei;
            s = (int)p[i];
            d = (int)p[(size_t)E + i];
        } else {
            const int* p = (const int*)ei;
            s = p[i];
            d = p[E + i];
        }
        // defensive clamp: never allow OOB addressing
        s = min(max(s, 0), N - 1);
        d = min(max(d, 0), N - 1);
    } else {
        s = i - E;
        d = i - E;
    }
    g_src[i] = s;
    g_dst[i] = d;
}

// zero den1 (4N floats), den2 (N), agg1 (128N), d_out (32N). i covers 32N float4s.
__global__ void k_zero_scratch(int N, float* __restrict__ out) {
    int i = blockIdx.x * blockDim.x + threadIdx.x;
    float4 z = make_float4(0.f, 0.f, 0.f, 0.f);
    if (i < 32 * N) reinterpret_cast<float4*>(g_agg1)[i] = z;      // 128N floats
    if (i < 8 * N)  reinterpret_cast<float4*>(out)[i] = z;         // 32N floats
    if (i < N) {
        reinterpret_cast<float4*>(g_den1)[i] = z;                  // 4N floats
        g_den2[i] = 0.f;
    }
}

// GEMM1: h1 = x @ W1 ([N,128]@[128,128]); also s_src1/s_dst1 per (node, head).
// 128 threads, 32 nodes/block. thread t: node t>>2, head/col-group t&3 (32 cols).
__global__ void k_gemm1(const float* __restrict__ x, const float* __restrict__ W,
                        const float* __restrict__ asrc, const float* __restrict__ adst,
                        int N) {
    extern __shared__ float sm[];
    float* Ws = sm;              // 128*128
    float* xs = sm + 16384;      // 32*132 (padded stride)
    int t = threadIdx.x;
    int base = blockIdx.x * 32;

    for (int i = t; i < 16384; i += 128) Ws[i] = W[i];
    for (int i = t; i < 4096; i += 128) {
        int n = i >> 7, k = i & 127;
        float v = (base + n < N) ? x[(size_t)(base + n) * 128 + k] : 0.f;
        xs[n * 132 + k] = v;
    }
    __syncthreads();

    int nl = t >> 2, cg = t & 3, c0 = cg * 32;
    float acc[32];
#pragma unroll
    for (int c = 0; c < 32; c++) acc[c] = 0.f;

#pragma unroll 4
    for (int k = 0; k < 128; k++) {
        float xv = xs[nl * 132 + k];
        const float4* wr = reinterpret_cast<const float4*>(Ws + k * 128 + c0);
#pragma unroll
        for (int q = 0; q < 8; q++) {
            float4 w = wr[q];
            acc[4 * q + 0] += xv * w.x;
            acc[4 * q + 1] += xv * w.y;
            acc[4 * q + 2] += xv * w.z;
            acc[4 * q + 3] += xv * w.w;
        }
    }

    int n = base + nl;
    if (n < N) {
        float ss = 0.f, sd = 0.f;
#pragma unroll
        for (int c = 0; c < 32; c++) {
            ss += acc[c] * asrc[c0 + c];   // head == cg since C==32
            sd += acc[c] * adst[c0 + c];
        }
        float4* out = reinterpret_cast<float4*>(g_h1 + (size_t)n * 128 + c0);
#pragma unroll
        for (int q = 0; q < 8; q++)
            out[q] = make_float4(acc[4 * q], acc[4 * q + 1], acc[4 * q + 2], acc[4 * q + 3]);
        g_ssrc1[n * 4 + cg] = ss;
        g_sdst1[n * 4 + cg] = sd;
    }
}

// Edge pass A, layer 1: e_exp per (edge, head), accumulate denom[dst,head].
__global__ void k_edgeA1(int etot) {
    int i = blockIdx.x * blockDim.x + threadIdx.x;
    if (i >= etot) return;
    int s = g_src[i], d = g_dst[i];
    float4 a = *reinterpret_cast<const float4*>(g_ssrc1 + (size_t)s * 4);
    float4 b = *reinterpret_cast<const float4*>(g_sdst1 + (size_t)d * 4);
    float4 e;
    e.x = __expf(lrelu(a.x + b.x));
    e.y = __expf(lrelu(a.y + b.y));
    e.z = __expf(lrelu(a.z + b.z));
    e.w = __expf(lrelu(a.w + b.w));
    *reinterpret_cast<float4*>(g_eexp + (size_t)i * 4) = e;
    red_add_v4(g_den1 + (size_t)d * 4, e.x, e.y, e.z, e.w);
}

// Edge pass B, layer 1: one warp per edge; lane l handles float4 at 4l (head = l>>3).
__global__ void k_edgeB1(int etot) {
    int gw = (blockIdx.x * blockDim.x + threadIdx.x) >> 5;
    if (gw >= etot) return;
    int lane = threadIdx.x & 31;
    int s = __ldg(g_src + gw), d = __ldg(g_dst + gw);
    int h = lane >> 3;
    float alpha = __ldg(g_eexp + (size_t)gw * 4 + h) /
                  (__ldg(g_den1 + (size_t)d * 4 + h) + 1e-16f);
    float4 hv = *reinterpret_cast<const float4*>(g_h1 + (size_t)s * 128 + lane * 4);
    red_add_v4(g_agg1 + (size_t)d * 128 + lane * 4,
               hv.x * alpha, hv.y * alpha, hv.z * alpha, hv.w * alpha);
}

// Node kernel: h1b = elu(agg1 + b1); h2 = h1b @ W2 ([N,128]@[128,32]); s_src2/s_dst2.
// 256 threads, 32 nodes/block. thread: node t>>3, 4 cols at (t&7)*4.
__global__ void k_layer2_node(const float* __restrict__ b1, const float* __restrict__ W2,
                              const float* __restrict__ asrc2, const float* __restrict__ adst2,
                              int N) {
    __shared__ float Ws[128 * 32];
    __shared__ float xs[32 * 132];
    __shared__ float sa[32], sb[32];
    int t = threadIdx.x;
    int base = blockIdx.x * 32;

    for (int i = t; i < 4096; i += 256) Ws[i] = W2[i];
    if (t < 32) { sa[t] = asrc2[t]; sb[t] = adst2[t]; }
    for (int i = t; i < 4096; i += 256) {
        int n = i >> 7, k = i & 127;
        float v = 0.f;
        if (base + n < N) {
            v = g_agg1[(size_t)(base + n) * 128 + k] + b1[k];
            v = v > 0.f ? v : expm1f(v);
        }
        xs[n * 132 + k] = v;
    }
    __syncthreads();

    int nl = t >> 3, cg = t & 7, c0 = cg * 4;
    float a0 = 0.f, a1 = 0.f, a2 = 0.f, a3 = 0.f;
#pragma unroll 4
    for (int k = 0; k < 128; k++) {
        float xv = xs[nl * 132 + k];
        float4 w = reinterpret_cast<const float4*>(Ws + k * 32)[cg];
        a0 += xv * w.x; a1 += xv * w.y; a2 += xv * w.z; a3 += xv * w.w;
    }

    float ps = a0 * sa[c0] + a1 * sa[c0 + 1] + a2 * sa[c0 + 2] + a3 * sa[c0 + 3];
    float pd = a0 * sb[c0] + a1 * sb[c0 + 1] + a2 * sb[c0 + 2] + a3 * sb[c0 + 3];
#pragma unroll
    for (int off = 4; off; off >>= 1) {
        ps += __shfl_xor_sync(0xffffffffu, ps, off);
        pd += __shfl_xor_sync(0xffffffffu, pd, off);
    }
    int n = base + nl;
    if (n < N) {
        *reinterpret_cast<float4*>(g_h2 + (size_t)n * 32 + c0) = make_float4(a0, a1, a2, a3);
        if (cg == 0) { g_ssrc2[n] = ps; g_sdst2[n] = pd; }
    }
}

// Edge pass A, layer 2 (H=1).
__global__ void k_edgeA2(int etot) {
    int i = blockIdx.x * blockDim.x + threadIdx.x;
    if (i >= etot) return;
    int s = g_src[i], d = g_dst[i];
    float e = __expf(lrelu(g_ssrc2[s] + g_sdst2[d]));
    g_eexp[i] = e;
    atomicAdd(g_den2 + d, e);
}

// Edge pass B, layer 2: 8 lanes per edge (32 floats/edge).
__global__ void k_edgeB2(float* __restrict__ out, int etot) {
    int g = (blockIdx.x * blockDim.x + threadIdx.x) >> 3;
    if (g >= etot) return;
    int sub = threadIdx.x & 7;
    int s = __ldg(g_src + g), d = __ldg(g_dst + g);
    float alpha = __ldg(g_eexp + g) / (__ldg(g_den2 + d) + 1e-16f);
    float4 hv = *reinterpret_cast<const float4*>(g_h2 + (size_t)s * 32 + sub * 4);
    red_add_v4(out + (size_t)d * 32 + sub * 4,
               hv.x * alpha, hv.y * alpha, hv.z * alpha, hv.w * alpha);
}

__global__ void k_add_bias(float* __restrict__ out, const float* __restrict__ b2, int n) {
    int i = blockIdx.x * blockDim.x + threadIdx.x;
    if (i < n) out[i] += b2[i & 31];
}

// ---------------- launch -----------------------------------------------------
extern "C" void kernel_launch(void* const* d_in, const int* in_sizes, int n_in,
                              void* d_out, int out_size) {
    const float* x     = (const float*)d_in[0];
    const void*  ei    = d_in[1];
    const float* W1    = (const float*)d_in[2];
    const float* asrc1 = (const float*)d_in[3];
    const float* adst1 = (const float*)d_in[4];
    const float* b1    = (const float*)d_in[5];
    const float* W2    = (const float*)d_in[6];
    const float* asrc2 = (const float*)d_in[7];
    const float* adst2 = (const float*)d_in[8];
    const float* b2    = (const float*)d_in[9];
    float* out = (float*)d_out;

    int N = in_sizes[0] / 128;
    int E = in_sizes[1] / 2;
    if (N > NMAX) N = NMAX;
    if (E > EMAX) E = EMAX;
    int etot = E + N;

    cudaFuncSetAttribute(k_gemm1, cudaFuncAttributeMaxDynamicSharedMemorySize, 90 * 1024);
    const int gemm1_smem = (16384 + 32 * 132) * 4;

    k_detect_dtype<<<1, 32>>>((const int*)ei);
    k_build_edges<<<(etot + 255) / 256, 256>>>(ei, E, N);
    k_zero_scratch<<<(32 * N + 255) / 256, 256>>>(N, out);
    // layer 1
    k_gemm1<<<(N + 31) / 32, 128, gemm1_smem>>>(x, W1, asrc1, adst1, N);
    k_edgeA1<<<(etot + 255) / 256, 256>>>(etot);
    k_edgeB1<<<(int)(((long long)etot * 32 + 255) / 256), 256>>>(etot);
    // layer 2
    k_layer2_node<<<(N + 31) / 32, 256>>>(b1, W2, asrc2, adst2, N);
    k_edgeA2<<<(etot + 255) / 256, 256>>>(etot);
    k_edgeB2<<<(int)(((long long)etot * 8 + 255) / 256), 256>>>(out, etot);
    // bias
    k_add_bias<<<(32 * N + 255) / 256, 256>>>(out, b2, 32 * N);
}

// round 4
// speedup vs baseline: 2.1391x; 2.1391x over previous
#include <cuda_runtime.h>
#include <cuda_bf16.h>
#include <cstdint>
#include <cstdio>

#define NMAX 100000
#define EMAX 1600000
#define ETMAX (EMAX + NMAX)

// ---------------- scratch (device globals; no allocation allowed) ----------
__device__ __align__(256) float g_h1  [(size_t)NMAX * 128];
__device__ __align__(256) float g_agg1[(size_t)NMAX * 128];
__device__ __align__(256) float g_h2  [(size_t)NMAX * 32];
__device__ __align__(256) float g_ssrc1[NMAX * 4];
__device__ __align__(256) float g_sdst1[NMAX * 4];
__device__ __align__(256) float g_den1 [NMAX * 4];
__device__ __align__(256) float g_ssrc2[NMAX];
__device__ __align__(256) float g_sdst2[NMAX];
__device__ __align__(256) float g_den2 [NMAX];
__device__ __align__(256) float g_eexp[(size_t)ETMAX * 4];
__device__ __align__(256) int   g_src[ETMAX];
__device__ __align__(256) int   g_dst[ETMAX];
__device__ int g_is64;

// ---------------- helpers ---------------------------------------------------
__device__ __forceinline__ float lrelu(float v) { return v > 0.f ? v : 0.2f * v; }

__device__ __forceinline__ void red_add_v4(float* addr, float a, float b, float c, float d) {
    asm volatile("red.global.add.v4.f32 [%0], {%1,%2,%3,%4};"
                 :: "l"(addr), "f"(a), "f"(b), "f"(c), "f"(d) : "memory");
}

// ---------------- setup kernels ---------------------------------------------
__global__ void k_detect_dtype(const int* __restrict__ ei32) {
    if (threadIdx.x == 0 && blockIdx.x == 0) {
        int all_zero = 1;
        for (int i = 0; i < 64; i++)
            if (ei32[2 * i + 1] != 0) { all_zero = 0; break; }
        g_is64 = all_zero;
    }
}

__global__ void k_build_edges(const void* __restrict__ ei, int E, int N) {
    int i = blockIdx.x * blockDim.x + threadIdx.x;
    int etot = E + N;
    if (i >= etot) return;
    int s, d;
    if (i < E) {
        if (g_is64) {
            const long long* p = (const long long*)ei;
            s = (int)p[i];
            d = (int)p[(size_t)E + i];
        } else {
            const int* p = (const int*)ei;
            s = p[i];
            d = p[E + i];
        }
        s = min(max(s, 0), N - 1);
        d = min(max(d, 0), N - 1);
    } else {
        s = i - E;
        d = i - E;
    }
    g_src[i] = s;
    g_dst[i] = d;
}

__global__ void k_zero_scratch(int N, float* __restrict__ out) {
    int i = blockIdx.x * blockDim.x + threadIdx.x;
    float4 z = make_float4(0.f, 0.f, 0.f, 0.f);
    if (i < 32 * N) reinterpret_cast<float4*>(g_agg1)[i] = z;
    if (i < 8 * N)  reinterpret_cast<float4*>(out)[i] = z;
    if (i < N) {
        reinterpret_cast<float4*>(g_den1)[i] = z;
        g_den2[i] = 0.f;
    }
}

// ---------------- GEMM1: register-blocked 128x128 tile ----------------------
// 256 threads = 16x16. Thread (tx,ty): rows {ty*4+i, 64+ty*4+i}, cols {tx*4+j, 64+tx*4+j}.
// K chunked by 16, smem double-buffered via register prefetch.
#define XP 136   // padded row stride for xs (k-major)

__global__ __launch_bounds__(256, 2)
void k_gemm1(const float* __restrict__ x, const float* __restrict__ W,
             const float* __restrict__ asrc, const float* __restrict__ adst, int N) {
    __shared__ float xs[2][16 * XP];     // xs[buf][k*XP + row]
    __shared__ float ws[2][16 * 128];    // ws[buf][k*128 + col]
    __shared__ float sa[128], sb[128];
    __shared__ float ssb[128 * 4], sdb[128 * 4];   // per-(row,head) dot accumulators

    int t = threadIdx.x;
    int base = blockIdx.x * 128;
    int tx = t & 15, ty = t >> 4;

    if (t < 128) { sa[t] = asrc[t]; sb[t] = adst[t]; }
    ssb[t] = 0.f; ssb[t + 256] = 0.f;
    sdb[t] = 0.f; sdb[t + 256] = 0.f;

    const float4* W4 = reinterpret_cast<const float4*>(W);

    float4 px0, px1, pw0, pw1;
    // x chunk loader: 512 float4s; id: row=id>>2 (0..127), kq=id&3
    auto ldx = [&](int k0, int id) -> float4 {
        int row = id >> 2, kq = id & 3;
        int gr = base + row;
        if (gr < N) return *reinterpret_cast<const float4*>(x + (size_t)gr * 128 + k0 + kq * 4);
        return make_float4(0.f, 0.f, 0.f, 0.f);
    };

    px0 = ldx(0, t); px1 = ldx(0, t + 256);
    pw0 = W4[t]; pw1 = W4[t + 256];

    float acc[8][8];
#pragma unroll
    for (int i = 0; i < 8; i++)
#pragma unroll
        for (int j = 0; j < 8; j++) acc[i][j] = 0.f;

    // store prefetched chunk into buffer
    auto sts = [&](int buf) {
        {
            int id = t, row = id >> 2, kq = id & 3;
            float* p = &xs[buf][(kq * 4) * XP + row];
            p[0] = px0.x; p[XP] = px0.y; p[2 * XP] = px0.z; p[3 * XP] = px0.w;
        }
        {
            int id = t + 256, row = id >> 2, kq = id & 3;
            float* p = &xs[buf][(kq * 4) * XP + row];
            p[0] = px1.x; p[XP] = px1.y; p[2 * XP] = px1.z; p[3 * XP] = px1.w;
        }
        reinterpret_cast<float4*>(ws[buf])[t] = pw0;
        reinterpret_cast<float4*>(ws[buf])[t + 256] = pw1;
    };

    sts(0);
    __syncthreads();

#pragma unroll 1
    for (int c = 0; c < 8; c++) {
        int buf = c & 1;
        if (c < 7) {
            int k0 = (c + 1) * 16;
            px0 = ldx(k0, t); px1 = ldx(k0, t + 256);
            pw0 = W4[k0 * 32 + t]; pw1 = W4[k0 * 32 + t + 256];
        }
#pragma unroll
        for (int k = 0; k < 16; k++) {
            float4 xa = *reinterpret_cast<const float4*>(&xs[buf][k * XP + tx * 0 + ty * 4]);
            float4 xb = *reinterpret_cast<const float4*>(&xs[buf][k * XP + 64 + ty * 4]);
            float4 wa = *reinterpret_cast<const float4*>(&ws[buf][k * 128 + tx * 4]);
            float4 wb = *reinterpret_cast<const float4*>(&ws[buf][k * 128 + 64 + tx * 4]);
            float xv[8] = {xa.x, xa.y, xa.z, xa.w, xb.x, xb.y, xb.z, xb.w};
            float wv[8] = {wa.x, wa.y, wa.z, wa.w, wb.x, wb.y, wb.z, wb.w};
#pragma unroll
            for (int i = 0; i < 8; i++)
#pragma unroll
                for (int j = 0; j < 8; j++)
                    acc[i][j] += xv[i] * wv[j];
        }
        __syncthreads();
        if (c < 7) { sts(buf ^ 1); __syncthreads(); }
    }

    // epilogue: write h1 tiles + accumulate attention dots into smem
    int hlo = tx >> 3;          // head of cols tx*4..+4   (0 or 1)
    int hhi = 2 + (tx >> 3);    // head of cols 64+tx*4..+4 (2 or 3)
#pragma unroll
    for (int half = 0; half < 2; half++) {
        int rbase = half * 64 + ty * 4;
#pragma unroll
        for (int i = 0; i < 4; i++) {
            int r = rbase + i;
            int gr = base + r;
            const float* ai = acc[half * 4 + i];
            if (gr < N) {
                *reinterpret_cast<float4*>(g_h1 + (size_t)gr * 128 + tx * 4) =
                    make_float4(ai[0], ai[1], ai[2], ai[3]);
                *reinterpret_cast<float4*>(g_h1 + (size_t)gr * 128 + 64 + tx * 4) =
                    make_float4(ai[4], ai[5], ai[6], ai[7]);
            }
            float ssl = ai[0] * sa[tx * 4] + ai[1] * sa[tx * 4 + 1] + ai[2] * sa[tx * 4 + 2] + ai[3] * sa[tx * 4 + 3];
            float ssh = ai[4] * sa[64 + tx * 4] + ai[5] * sa[64 + tx * 4 + 1] + ai[6] * sa[64 + tx * 4 + 2] + ai[7] * sa[64 + tx * 4 + 3];
            float sdl = ai[0] * sb[tx * 4] + ai[1] * sb[tx * 4 + 1] + ai[2] * sb[tx * 4 + 2] + ai[3] * sb[tx * 4 + 3];
            float sdh = ai[4] * sb[64 + tx * 4] + ai[5] * sb[64 + tx * 4 + 1] + ai[6] * sb[64 + tx * 4 + 2] + ai[7] * sb[64 + tx * 4 + 3];
            atomicAdd(&ssb[r * 4 + hlo], ssl);
            atomicAdd(&ssb[r * 4 + hhi], ssh);
            atomicAdd(&sdb[r * 4 + hlo], sdl);
            atomicAdd(&sdb[r * 4 + hhi], sdh);
        }
    }
    __syncthreads();
    if (t < 128) {
        int gr = base + t;
        if (gr < N) {
            *reinterpret_cast<float4*>(g_ssrc1 + (size_t)gr * 4) =
                *reinterpret_cast<const float4*>(ssb + t * 4);
            *reinterpret_cast<float4*>(g_sdst1 + (size_t)gr * 4) =
                *reinterpret_cast<const float4*>(sdb + t * 4);
        }
    }
}

// ---------------- edge passes, layer 1 --------------------------------------
__global__ void k_edgeA1(int etot) {
    int i = blockIdx.x * blockDim.x + threadIdx.x;
    if (i >= etot) return;
    int s = g_src[i], d = g_dst[i];
    float4 a = *reinterpret_cast<const float4*>(g_ssrc1 + (size_t)s * 4);
    float4 b = *reinterpret_cast<const float4*>(g_sdst1 + (size_t)d * 4);
    float4 e;
    e.x = __expf(lrelu(a.x + b.x));
    e.y = __expf(lrelu(a.y + b.y));
    e.z = __expf(lrelu(a.z + b.z));
    e.w = __expf(lrelu(a.w + b.w));
    *reinterpret_cast<float4*>(g_eexp + (size_t)i * 4) = e;
    red_add_v4(g_den1 + (size_t)d * 4, e.x, e.y, e.z, e.w);
}

__global__ void k_edgeB1(int etot) {
    int gw = (blockIdx.x * blockDim.x + threadIdx.x) >> 5;
    if (gw >= etot) return;
    int lane = threadIdx.x & 31;
    int s = __ldg(g_src + gw), d = __ldg(g_dst + gw);
    int h = lane >> 3;
    float alpha = __ldg(g_eexp + (size_t)gw * 4 + h) /
                  (__ldg(g_den1 + (size_t)d * 4 + h) + 1e-16f);
    float4 hv = *reinterpret_cast<const float4*>(g_h1 + (size_t)s * 128 + lane * 4);
    red_add_v4(g_agg1 + (size_t)d * 128 + lane * 4,
               hv.x * alpha, hv.y * alpha, hv.z * alpha, hv.w * alpha);
}

// ---------------- layer 2 node kernel: elu + GEMM [N,128]@[128,32] ----------
// 256 threads: tx 0..7 (cols tx*4), ty 0..31 (rows {ty*4+i, 128+ty*4+i}). Tile M=256.
#define XP2 264

__global__ __launch_bounds__(256, 2)
void k_layer2_node(const float* __restrict__ b1, const float* __restrict__ W2,
                   const float* __restrict__ asrc2, const float* __restrict__ adst2,
                   int N) {
    __shared__ float xs[16 * XP2];       // xs[k*XP2 + row], one chunk
    __shared__ float ws[128 * 32];       // full W2
    __shared__ float sb1[128];
    __shared__ float sa[32], sb[32];

    int t = threadIdx.x;
    int base = blockIdx.x * 256;
    int tx = t & 7, ty = t >> 3;

    if (t < 128) sb1[t] = b1[t];
    if (t < 32) { sa[t] = asrc2[t]; sb[t] = adst2[t]; }
    for (int i = t; i < 1024; i += 256)
        reinterpret_cast<float4*>(ws)[i] = reinterpret_cast<const float4*>(W2)[i];

    // chunk loader: 1024 float4s; id: row=id>>2 (0..255), kq=id&3; applies bias+ELU
    float4 pf[4];
    auto ldx = [&](int k0, int id) -> float4 {
        int row = id >> 2, kq = id & 3;
        int gr = base + row;
        float4 v = make_float4(0.f, 0.f, 0.f, 0.f);
        if (gr < N) {
            v = *reinterpret_cast<const float4*>(g_agg1 + (size_t)gr * 128 + k0 + kq * 4);
            v.x += sb1[k0 + kq * 4];     v.x = v.x > 0.f ? v.x : expm1f(v.x);
            v.y += sb1[k0 + kq * 4 + 1]; v.y = v.y > 0.f ? v.y : expm1f(v.y);
            v.z += sb1[k0 + kq * 4 + 2]; v.z = v.z > 0.f ? v.z : expm1f(v.z);
            v.w += sb1[k0 + kq * 4 + 3]; v.w = v.w > 0.f ? v.w : expm1f(v.w);
        }
        return v;
    };
    __syncthreads();   // sb1 ready before ldx uses it

#pragma unroll
    for (int j = 0; j < 4; j++) pf[j] = ldx(0, t + 256 * j);

    float acc[8][4];
#pragma unroll
    for (int i = 0; i < 8; i++)
#pragma unroll
        for (int j = 0; j < 4; j++) acc[i][j] = 0.f;

#pragma unroll 1
    for (int c = 0; c < 8; c++) {
        // store prefetched chunk
        __syncthreads();
#pragma unroll
        for (int j = 0; j < 4; j++) {
            int id = t + 256 * j, row = id >> 2, kq = id & 3;
            float* p = &xs[(kq * 4) * XP2 + row];
            p[0] = pf[j].x; p[XP2] = pf[j].y; p[2 * XP2] = pf[j].z; p[3 * XP2] = pf[j].w;
        }
        __syncthreads();
        if (c < 7) {
            int k0 = (c + 1) * 16;
#pragma unroll
            for (int j = 0; j < 4; j++) pf[j] = ldx(k0, t + 256 * j);
        }
        int kb = c * 16;
#pragma unroll
        for (int k = 0; k < 16; k++) {
            float4 xa = *reinterpret_cast<const float4*>(&xs[k * XP2 + ty * 4]);
            float4 xb = *reinterpret_cast<const float4*>(&xs[k * XP2 + 128 + ty * 4]);
            float4 wv = *reinterpret_cast<const float4*>(&ws[(kb + k) * 32 + tx * 4]);
            float xv[8] = {xa.x, xa.y, xa.z, xa.w, xb.x, xb.y, xb.z, xb.w};
#pragma unroll
            for (int i = 0; i < 8; i++) {
                acc[i][0] += xv[i] * wv.x;
                acc[i][1] += xv[i] * wv.y;
                acc[i][2] += xv[i] * wv.z;
                acc[i][3] += xv[i] * wv.w;
            }
        }
    }

    // epilogue: write h2, reduce attention dots across tx lanes (8 per row group)
#pragma unroll
    for (int half = 0; half < 2; half++) {
#pragma unroll
        for (int i = 0; i < 4; i++) {
            int r = half * 128 + ty * 4 + i;
            int gr = base + r;
            const float* ai = acc[half * 4 + i];
            if (gr < N)
                *reinterpret_cast<float4*>(g_h2 + (size_t)gr * 32 + tx * 4) =
                    make_float4(ai[0], ai[1], ai[2], ai[3]);
            float ps = ai[0] * sa[tx * 4] + ai[1] * sa[tx * 4 + 1] + ai[2] * sa[tx * 4 + 2] + ai[3] * sa[tx * 4 + 3];
            float pd = ai[0] * sb[tx * 4] + ai[1] * sb[tx * 4 + 1] + ai[2] * sb[tx * 4 + 2] + ai[3] * sb[tx * 4 + 3];
#pragma unroll
            for (int off = 4; off; off >>= 1) {
                ps += __shfl_xor_sync(0xffffffffu, ps, off);
                pd += __shfl_xor_sync(0xffffffffu, pd, off);
            }
            if (tx == 0 && gr < N) { g_ssrc2[gr] = ps; g_sdst2[gr] = pd; }
        }
    }
}

// ---------------- edge passes, layer 2 --------------------------------------
__global__ void k_edgeA2(int etot) {
    int i = blockIdx.x * blockDim.x + threadIdx.x;
    if (i >= etot) return;
    int s = g_src[i], d = g_dst[i];
    float e = __expf(lrelu(g_ssrc2[s] + g_sdst2[d]));
    g_eexp[i] = e;
    atomicAdd(g_den2 + d, e);
}

__global__ void k_edgeB2(float* __restrict__ out, int etot) {
    int g = (blockIdx.x * blockDim.x + threadIdx.x) >> 3;
    if (g >= etot) return;
    int sub = threadIdx.x & 7;
    int s = __ldg(g_src + g), d = __ldg(g_dst + g);
    float alpha = __ldg(g_eexp + g) / (__ldg(g_den2 + d) + 1e-16f);
    float4 hv = *reinterpret_cast<const float4*>(g_h2 + (size_t)s * 32 + sub * 4);
    red_add_v4(out + (size_t)d * 32 + sub * 4,
               hv.x * alpha, hv.y * alpha, hv.z * alpha, hv.w * alpha);
}

__global__ void k_add_bias(float* __restrict__ out, const float* __restrict__ b2, int n) {
    int i = blockIdx.x * blockDim.x + threadIdx.x;
    if (i < n) out[i] += b2[i & 31];
}

// ---------------- launch -----------------------------------------------------
extern "C" void kernel_launch(void* const* d_in, const int* in_sizes, int n_in,
                              void* d_out, int out_size) {
    const float* x     = (const float*)d_in[0];
    const void*  ei    = d_in[1];
    const float* W1    = (const float*)d_in[2];
    const float* asrc1 = (const float*)d_in[3];
    const float* adst1 = (const float*)d_in[4];
    const float* b1    = (const float*)d_in[5];
    const float* W2    = (const float*)d_in[6];
    const float* asrc2 = (const float*)d_in[7];
    const float* adst2 = (const float*)d_in[8];
    const float* b2    = (const float*)d_in[9];
    float* out = (float*)d_out;

    int N = in_sizes[0] / 128;
    int E = in_sizes[1] / 2;
    if (N > NMAX) N = NMAX;
    if (E > EMAX) E = EMAX;
    int etot = E + N;

    k_detect_dtype<<<1, 32>>>((const int*)ei);
    k_build_edges<<<(etot + 255) / 256, 256>>>(ei, E, N);
    k_zero_scratch<<<(32 * N + 255) / 256, 256>>>(N, out);
    // layer 1
    k_gemm1<<<(N + 127) / 128, 256>>>(x, W1, asrc1, adst1, N);
    k_edgeA1<<<(etot + 255) / 256, 256>>>(etot);
    k_edgeB1<<<(int)(((long long)etot * 32 + 255) / 256), 256>>>(etot);
    // layer 2
    k_layer2_node<<<(N + 255) / 256, 256>>>(b1, W2, asrc2, adst2, N);
    k_edgeA2<<<(etot + 255) / 256, 256>>>(etot);
    k_edgeB2<<<(int)(((long long)etot * 8 + 255) / 256), 256>>>(out, etot);
    // bias
    k_add_bias<<<(32 * N + 255) / 256, 256>>>(out, b2, 32 * N);
}

// round 5
// speedup vs baseline: 2.9142x; 1.3623x over previous
#include <cuda_runtime.h>
#include <cuda_bf16.h>
#include <cstdint>
#include <cstdio>

#define NMAX 100000
#define EMAX 1600000
#define ETMAX (EMAX + NMAX)
#define NBLK ((NMAX + 255) / 256)   // scan blocks (391)

// ---------------- scratch (device globals) ----------------------------------
__device__ __align__(256) float g_h1  [(size_t)NMAX * 128];
__device__ __align__(256) float g_agg1[(size_t)NMAX * 128];
__device__ __align__(256) float g_h2  [(size_t)NMAX * 32];
__device__ __align__(256) float g_ssrc1[NMAX * 4];
__device__ __align__(256) float g_sdst1[NMAX * 4];
__device__ __align__(256) float g_ssrc2[NMAX];
__device__ __align__(256) float g_sdst2[NMAX];
__device__ __align__(256) float g_eexp[(size_t)ETMAX * 4];   // CSR-ordered e4
__device__ __align__(256) int   g_src[ETMAX];
__device__ __align__(256) int   g_dst[ETMAX];
__device__ __align__(256) int   g_csr_src[ETMAX];
__device__ __align__(256) int   g_deg[NMAX];
__device__ __align__(256) int   g_ebefore[NMAX];
__device__ __align__(256) int   g_rowptr[NMAX];
__device__ __align__(256) int   g_cursor[NMAX];
__device__ __align__(256) int   g_blocksum[512];
__device__ __align__(256) int   g_bsumex[512];
__device__ int g_is64;

// ---------------- helpers ---------------------------------------------------
__device__ __forceinline__ float lrelu(float v) { return v > 0.f ? v : 0.2f * v; }

// ---------------- setup ------------------------------------------------------
__global__ void k_detect_dtype(const int* __restrict__ ei32) {
    if (threadIdx.x == 0 && blockIdx.x == 0) {
        int all_zero = 1;
        for (int i = 0; i < 64; i++)
            if (ei32[2 * i + 1] != 0) { all_zero = 0; break; }
        g_is64 = all_zero;
    }
}

__global__ void k_zero_deg(int N) {
    int i = blockIdx.x * blockDim.x + threadIdx.x;
    if (i < N) g_deg[i] = 0;
}

// edges -> int32 + self loops, fused degree histogram
__global__ void k_build_edges(const void* __restrict__ ei, int E, int N) {
    int i = blockIdx.x * blockDim.x + threadIdx.x;
    int etot = E + N;
    if (i >= etot) return;
    int s, d;
    if (i < E) {
        if (g_is64) {
            const long long* p = (const long long*)ei;
            s = (int)p[i];
            d = (int)p[(size_t)E + i];
        } else {
            const int* p = (const int*)ei;
            s = p[i];
            d = p[E + i];
        }
        s = min(max(s, 0), N - 1);
        d = min(max(d, 0), N - 1);
    } else {
        s = i - E;
        d = i - E;
    }
    g_src[i] = s;
    g_dst[i] = d;
    atomicAdd(&g_deg[d], 1);
}

// ---------------- exclusive scan of deg (3 kernels) --------------------------
__global__ void k_scan1(int N) {
    __shared__ int sm[256];
    int t = threadIdx.x;
    int idx = blockIdx.x * 256 + t;
    int v = (idx < N) ? g_deg[idx] : 0;
    sm[t] = v;
    __syncthreads();
#pragma unroll
    for (int off = 1; off < 256; off <<= 1) {
        int add = (t >= off) ? sm[t - off] : 0;
        __syncthreads();
        sm[t] += add;
        __syncthreads();
    }
    if (idx < N) g_ebefore[idx] = sm[t] - v;
    if (t == 255) g_blocksum[blockIdx.x] = sm[255];
}

__global__ void k_scan2(int nb) {
    __shared__ int sm[512];
    int t = threadIdx.x;
    int v = (t < nb) ? g_blocksum[t] : 0;
    sm[t] = v;
    __syncthreads();
#pragma unroll
    for (int off = 1; off < 512; off <<= 1) {
        int add = (t >= off) ? sm[t - off] : 0;
        __syncthreads();
        sm[t] += add;
        __syncthreads();
    }
    if (t < nb) g_bsumex[t] = sm[t] - v;
}

__global__ void k_scan3(int N) {
    int i = blockIdx.x * blockDim.x + threadIdx.x;
    if (i >= N) return;
    int r = g_ebefore[i] + g_bsumex[i >> 8];
    g_rowptr[i] = r;
    g_cursor[i] = r;
}

// ---------------- GEMM1: register-blocked 128x128 tile ----------------------
#define XP 136

__global__ __launch_bounds__(256, 2)
void k_gemm1(const float* __restrict__ x, const float* __restrict__ W,
             const float* __restrict__ asrc, const float* __restrict__ adst, int N) {
    __shared__ float xs[2][16 * XP];
    __shared__ float ws[2][16 * 128];
    __shared__ float sa[128], sb[128];
    __shared__ float ssb[128 * 4], sdb[128 * 4];

    int t = threadIdx.x;
    int base = blockIdx.x * 128;
    int tx = t & 15, ty = t >> 4;

    if (t < 128) { sa[t] = asrc[t]; sb[t] = adst[t]; }
    ssb[t] = 0.f; ssb[t + 256] = 0.f;
    sdb[t] = 0.f; sdb[t + 256] = 0.f;

    const float4* W4 = reinterpret_cast<const float4*>(W);

    float4 px0, px1, pw0, pw1;
    auto ldx = [&](int k0, int id) -> float4 {
        int row = id >> 2, kq = id & 3;
        int gr = base + row;
        if (gr < N) return *reinterpret_cast<const float4*>(x + (size_t)gr * 128 + k0 + kq * 4);
        return make_float4(0.f, 0.f, 0.f, 0.f);
    };

    px0 = ldx(0, t); px1 = ldx(0, t + 256);
    pw0 = W4[t]; pw1 = W4[t + 256];

    float acc[8][8];
#pragma unroll
    for (int i = 0; i < 8; i++)
#pragma unroll
        for (int j = 0; j < 8; j++) acc[i][j] = 0.f;

    auto sts = [&](int buf) {
        {
            int id = t, row = id >> 2, kq = id & 3;
            float* p = &xs[buf][(kq * 4) * XP + row];
            p[0] = px0.x; p[XP] = px0.y; p[2 * XP] = px0.z; p[3 * XP] = px0.w;
        }
        {
            int id = t + 256, row = id >> 2, kq = id & 3;
            float* p = &xs[buf][(kq * 4) * XP + row];
            p[0] = px1.x; p[XP] = px1.y; p[2 * XP] = px1.z; p[3 * XP] = px1.w;
        }
        reinterpret_cast<float4*>(ws[buf])[t] = pw0;
        reinterpret_cast<float4*>(ws[buf])[t + 256] = pw1;
    };

    sts(0);
    __syncthreads();

#pragma unroll 1
    for (int c = 0; c < 8; c++) {
        int buf = c & 1;
        if (c < 7) {
            int k0 = (c + 1) * 16;
            px0 = ldx(k0, t); px1 = ldx(k0, t + 256);
            pw0 = W4[k0 * 32 + t]; pw1 = W4[k0 * 32 + t + 256];
        }
#pragma unroll
        for (int k = 0; k < 16; k++) {
            float4 xa = *reinterpret_cast<const float4*>(&xs[buf][k * XP + ty * 4]);
            float4 xb = *reinterpret_cast<const float4*>(&xs[buf][k * XP + 64 + ty * 4]);
            float4 wa = *reinterpret_cast<const float4*>(&ws[buf][k * 128 + tx * 4]);
            float4 wb = *reinterpret_cast<const float4*>(&ws[buf][k * 128 + 64 + tx * 4]);
            float xv[8] = {xa.x, xa.y, xa.z, xa.w, xb.x, xb.y, xb.z, xb.w};
            float wv[8] = {wa.x, wa.y, wa.z, wa.w, wb.x, wb.y, wb.z, wb.w};
#pragma unroll
            for (int i = 0; i < 8; i++)
#pragma unroll
                for (int j = 0; j < 8; j++)
                    acc[i][j] += xv[i] * wv[j];
        }
        __syncthreads();
        if (c < 7) { sts(buf ^ 1); __syncthreads(); }
    }

    int hlo = tx >> 3;
    int hhi = 2 + (tx >> 3);
#pragma unroll
    for (int half = 0; half < 2; half++) {
        int rbase = half * 64 + ty * 4;
#pragma unroll
        for (int i = 0; i < 4; i++) {
            int r = rbase + i;
            int gr = base + r;
            const float* ai = acc[half * 4 + i];
            if (gr < N) {
                *reinterpret_cast<float4*>(g_h1 + (size_t)gr * 128 + tx * 4) =
                    make_float4(ai[0], ai[1], ai[2], ai[3]);
                *reinterpret_cast<float4*>(g_h1 + (size_t)gr * 128 + 64 + tx * 4) =
                    make_float4(ai[4], ai[5], ai[6], ai[7]);
            }
            float ssl = ai[0] * sa[tx * 4] + ai[1] * sa[tx * 4 + 1] + ai[2] * sa[tx * 4 + 2] + ai[3] * sa[tx * 4 + 3];
            float ssh = ai[4] * sa[64 + tx * 4] + ai[5] * sa[64 + tx * 4 + 1] + ai[6] * sa[64 + tx * 4 + 2] + ai[7] * sa[64 + tx * 4 + 3];
            float sdl = ai[0] * sb[tx * 4] + ai[1] * sb[tx * 4 + 1] + ai[2] * sb[tx * 4 + 2] + ai[3] * sb[tx * 4 + 3];
            float sdh = ai[4] * sb[64 + tx * 4] + ai[5] * sb[64 + tx * 4 + 1] + ai[6] * sb[64 + tx * 4 + 2] + ai[7] * sb[64 + tx * 4 + 3];
            atomicAdd(&ssb[r * 4 + hlo], ssl);
            atomicAdd(&ssb[r * 4 + hhi], ssh);
            atomicAdd(&sdb[r * 4 + hlo], sdl);
            atomicAdd(&sdb[r * 4 + hhi], sdh);
        }
    }
    __syncthreads();
    if (t < 128) {
        int gr = base + t;
        if (gr < N) {
            *reinterpret_cast<float4*>(g_ssrc1 + (size_t)gr * 4) =
                *reinterpret_cast<const float4*>(ssb + t * 4);
            *reinterpret_cast<float4*>(g_sdst1 + (size_t)gr * 4) =
                *reinterpret_cast<const float4*>(sdb + t * 4);
        }
    }
}

// ---------------- scatter edges into CSR with fused e4 computation ----------
__global__ void k_scatterA1(int etot) {
    int i = blockIdx.x * blockDim.x + threadIdx.x;
    if (i >= etot) return;
    int s = g_src[i], d = g_dst[i];
    float4 a = *reinterpret_cast<const float4*>(g_ssrc1 + (size_t)s * 4);
    float4 b = *reinterpret_cast<const float4*>(g_sdst1 + (size_t)d * 4);
    float4 e;
    e.x = __expf(lrelu(a.x + b.x));
    e.y = __expf(lrelu(a.y + b.y));
    e.z = __expf(lrelu(a.z + b.z));
    e.w = __expf(lrelu(a.w + b.w));
    int pos = atomicAdd(&g_cursor[d], 1);
    g_csr_src[pos] = s;
    *reinterpret_cast<float4*>(g_eexp + (size_t)pos * 4) = e;
}

// ---------------- layer 1 aggregation: warp per dst, no atomics -------------
__global__ void k_agg1(int N) {
    int w = (blockIdx.x * blockDim.x + threadIdx.x) >> 5;
    if (w >= N) return;
    int lane = threadIdx.x & 31;
    int h = lane >> 3, c0 = lane * 4;
    int deg = g_deg[w], start = g_rowptr[w];
    const float4* e4 = reinterpret_cast<const float4*>(g_eexp);

    float den = 0.f;
    for (int j = 0; j < deg; j++) {
        float4 e = __ldg(&e4[start + j]);
        den += (h == 0) ? e.x : (h == 1) ? e.y : (h == 2) ? e.z : e.w;
    }
    float inv = 1.f / (den + 1e-16f);

    float4 acc = make_float4(0.f, 0.f, 0.f, 0.f);
    for (int j = 0; j < deg; j++) {
        float4 e = __ldg(&e4[start + j]);
        float eh = (h == 0) ? e.x : (h == 1) ? e.y : (h == 2) ? e.z : e.w;
        float alpha = eh * inv;
        int s = __ldg(&g_csr_src[start + j]);
        float4 hv = *reinterpret_cast<const float4*>(g_h1 + (size_t)s * 128 + c0);
        acc.x += alpha * hv.x;
        acc.y += alpha * hv.y;
        acc.z += alpha * hv.z;
        acc.w += alpha * hv.w;
    }
    *reinterpret_cast<float4*>(g_agg1 + (size_t)w * 128 + c0) = acc;
}

// ---------------- layer 2 node kernel: elu + GEMM [N,128]@[128,32] ----------
#define XP2 264

__global__ __launch_bounds__(256, 2)
void k_layer2_node(const float* __restrict__ b1, const float* __restrict__ W2,
                   const float* __restrict__ asrc2, const float* __restrict__ adst2,
                   int N) {
    __shared__ float xs[16 * XP2];
    __shared__ float ws[128 * 32];
    __shared__ float sb1[128];
    __shared__ float sa[32], sb[32];

    int t = threadIdx.x;
    int base = blockIdx.x * 256;
    int tx = t & 7, ty = t >> 3;

    if (t < 128) sb1[t] = b1[t];
    if (t < 32) { sa[t] = asrc2[t]; sb[t] = adst2[t]; }
    for (int i = t; i < 1024; i += 256)
        reinterpret_cast<float4*>(ws)[i] = reinterpret_cast<const float4*>(W2)[i];

    float4 pf[4];
    auto ldx = [&](int k0, int id) -> float4 {
        int row = id >> 2, kq = id & 3;
        int gr = base + row;
        float4 v = make_float4(0.f, 0.f, 0.f, 0.f);
        if (gr < N) {
            v = *reinterpret_cast<const float4*>(g_agg1 + (size_t)gr * 128 + k0 + kq * 4);
            v.x += sb1[k0 + kq * 4];     v.x = v.x > 0.f ? v.x : expm1f(v.x);
            v.y += sb1[k0 + kq * 4 + 1]; v.y = v.y > 0.f ? v.y : expm1f(v.y);
            v.z += sb1[k0 + kq * 4 + 2]; v.z = v.z > 0.f ? v.z : expm1f(v.z);
            v.w += sb1[k0 + kq * 4 + 3]; v.w = v.w > 0.f ? v.w : expm1f(v.w);
        }
        return v;
    };
    __syncthreads();

#pragma unroll
    for (int j = 0; j < 4; j++) pf[j] = ldx(0, t + 256 * j);

    float acc[8][4];
#pragma unroll
    for (int i = 0; i < 8; i++)
#pragma unroll
        for (int j = 0; j < 4; j++) acc[i][j] = 0.f;

#pragma unroll 1
    for (int c = 0; c < 8; c++) {
        __syncthreads();
#pragma unroll
        for (int j = 0; j < 4; j++) {
            int id = t + 256 * j, row = id >> 2, kq = id & 3;
            float* p = &xs[(kq * 4) * XP2 + row];
            p[0] = pf[j].x; p[XP2] = pf[j].y; p[2 * XP2] = pf[j].z; p[3 * XP2] = pf[j].w;
        }
        __syncthreads();
        if (c < 7) {
            int k0 = (c + 1) * 16;
#pragma unroll
            for (int j = 0; j < 4; j++) pf[j] = ldx(k0, t + 256 * j);
        }
        int kb = c * 16;
#pragma unroll
        for (int k = 0; k < 16; k++) {
            float4 xa = *reinterpret_cast<const float4*>(&xs[k * XP2 + ty * 4]);
            float4 xb = *reinterpret_cast<const float4*>(&xs[k * XP2 + 128 + ty * 4]);
            float4 wv = *reinterpret_cast<const float4*>(&ws[(kb + k) * 32 + tx * 4]);
            float xv[8] = {xa.x, xa.y, xa.z, xa.w, xb.x, xb.y, xb.z, xb.w};
#pragma unroll
            for (int i = 0; i < 8; i++) {
                acc[i][0] += xv[i] * wv.x;
                acc[i][1] += xv[i] * wv.y;
                acc[i][2] += xv[i] * wv.z;
                acc[i][3] += xv[i] * wv.w;
            }
        }
    }

#pragma unroll
    for (int half = 0; half < 2; half++) {
#pragma unroll
        for (int i = 0; i < 4; i++) {
            int r = half * 128 + ty * 4 + i;
            int gr = base + r;
            const float* ai = acc[half * 4 + i];
            if (gr < N)
                *reinterpret_cast<float4*>(g_h2 + (size_t)gr * 32 + tx * 4) =
                    make_float4(ai[0], ai[1], ai[2], ai[3]);
            float ps = ai[0] * sa[tx * 4] + ai[1] * sa[tx * 4 + 1] + ai[2] * sa[tx * 4 + 2] + ai[3] * sa[tx * 4 + 3];
            float pd = ai[0] * sb[tx * 4] + ai[1] * sb[tx * 4 + 1] + ai[2] * sb[tx * 4 + 2] + ai[3] * sb[tx * 4 + 3];
#pragma unroll
            for (int off = 4; off; off >>= 1) {
                ps += __shfl_xor_sync(0xffffffffu, ps, off);
                pd += __shfl_xor_sync(0xffffffffu, pd, off);
            }
            if (tx == 0 && gr < N) { g_ssrc2[gr] = ps; g_sdst2[gr] = pd; }
        }
    }
}

// ---------------- layer 2 aggregation: warp per dst, fused bias -------------
__global__ void k_agg2(float* __restrict__ out, const float* __restrict__ b2, int N) {
    int w = (blockIdx.x * blockDim.x + threadIdx.x) >> 5;
    if (w >= N) return;
    int lane = threadIdx.x & 31;
    int deg = g_deg[w], start = g_rowptr[w];
    float sd = g_sdst2[w];

    // denominator: lanes strided over edges, warp-reduce
    float p = 0.f;
    for (int j = lane; j < deg; j += 32) {
        int s = __ldg(&g_csr_src[start + j]);
        p += __expf(lrelu(__ldg(&g_ssrc2[s]) + sd));
    }
#pragma unroll
    for (int off = 16; off; off >>= 1) p += __shfl_xor_sync(0xffffffffu, p, off);
    float inv = 1.f / (p + 1e-16f);

    float acc = 0.f;
    for (int j = 0; j < deg; j++) {
        int s = __ldg(&g_csr_src[start + j]);
        float alpha = __expf(lrelu(__ldg(&g_ssrc2[s]) + sd)) * inv;
        acc += alpha * __ldg(&g_h2[(size_t)s * 32 + lane]);
    }
    out[(size_t)w * 32 + lane] = acc + __ldg(&b2[lane]);
}

// ---------------- launch -----------------------------------------------------
extern "C" void kernel_launch(void* const* d_in, const int* in_sizes, int n_in,
                              void* d_out, int out_size) {
    const float* x     = (const float*)d_in[0];
    const void*  ei    = d_in[1];
    const float* W1    = (const float*)d_in[2];
    const float* asrc1 = (const float*)d_in[3];
    const float* adst1 = (const float*)d_in[4];
    const float* b1    = (const float*)d_in[5];
    const float* W2    = (const float*)d_in[6];
    const float* asrc2 = (const float*)d_in[7];
    const float* adst2 = (const float*)d_in[8];
    const float* b2    = (const float*)d_in[9];
    float* out = (float*)d_out;

    int N = in_sizes[0] / 128;
    int E = in_sizes[1] / 2;
    if (N > NMAX) N = NMAX;
    if (E > EMAX) E = EMAX;
    int etot = E + N;
    int nb = (N + 255) / 256;

    k_detect_dtype<<<1, 32>>>((const int*)ei);
    k_zero_deg<<<(N + 255) / 256, 256>>>(N);
    k_build_edges<<<(etot + 255) / 256, 256>>>(ei, E, N);
    // CSR offsets
    k_scan1<<<nb, 256>>>(N);
    k_scan2<<<1, 512>>>(nb);
    k_scan3<<<(N + 255) / 256, 256>>>(N);
    // layer 1
    k_gemm1<<<(N + 127) / 128, 256>>>(x, W1, asrc1, adst1, N);
    k_scatterA1<<<(etot + 255) / 256, 256>>>(etot);
    k_agg1<<<(int)(((long long)N * 32 + 255) / 256), 256>>>(N);
    // layer 2
    k_layer2_node<<<(N + 255) / 256, 256>>>(b1, W2, asrc2, adst2, N);
    k_agg2<<<(int)(((long long)N * 32 + 255) / 256), 256>>>(out, b2, N);
}

// round 7
// speedup vs baseline: 3.7503x; 1.2869x over previous
#include <cuda_runtime.h>
#include <cuda_bf16.h>
#include <cstdint>
#include <cstdio>

#define NMAX 100000
#define EMAX 1600000
#define ETMAX (EMAX + NMAX)

// ---------------- scratch (device globals) ----------------------------------
__device__ __align__(256) float g_h1  [(size_t)NMAX * 128];
__device__ __align__(256) float g_agg1[(size_t)NMAX * 128];
__device__ __align__(256) float g_h2  [(size_t)NMAX * 32];
__device__ __align__(256) float g_ssrc1[NMAX * 4];
__device__ __align__(256) float g_sdst1[NMAX * 4];
__device__ __align__(256) float g_ssrc2[NMAX];
__device__ __align__(256) float g_sdst2[NMAX];
__device__ __align__(256) int   g_src[ETMAX];
__device__ __align__(256) int   g_dst[ETMAX];
__device__ __align__(256) int   g_csr_src[ETMAX];
__device__ __align__(256) int   g_deg[NMAX];
__device__ __align__(256) int   g_ebefore[NMAX];
__device__ __align__(256) int   g_rowptr[NMAX];
__device__ __align__(256) int   g_cursor[NMAX];
__device__ __align__(256) int   g_blocksum[512];
__device__ __align__(256) int   g_bsumex[512];
__device__ int g_is64;

// ---------------- helpers ---------------------------------------------------
__device__ __forceinline__ float lrelu(float v) { return v > 0.f ? v : 0.2f * v; }

// ---------------- setup ------------------------------------------------------
__global__ void k_detect_dtype(const int* __restrict__ ei32) {
    if (threadIdx.x == 0 && blockIdx.x == 0) {
        int all_zero = 1;
        for (int i = 0; i < 64; i++)
            if (ei32[2 * i + 1] != 0) { all_zero = 0; break; }
        g_is64 = all_zero;
    }
}

__global__ void k_zero_deg(int N) {
    int i = blockIdx.x * blockDim.x + threadIdx.x;
    if (i < N) g_deg[i] = 0;
}

__global__ void k_build_edges(const void* __restrict__ ei, int E, int N) {
    int i = blockIdx.x * blockDim.x + threadIdx.x;
    int etot = E + N;
    if (i >= etot) return;
    int s, d;
    if (i < E) {
        if (g_is64) {
            const long long* p = (const long long*)ei;
            s = (int)p[i];
            d = (int)p[(size_t)E + i];
        } else {
            const int* p = (const int*)ei;
            s = p[i];
            d = p[E + i];
        }
        s = min(max(s, 0), N - 1);
        d = min(max(d, 0), N - 1);
    } else {
        s = i - E;
        d = i - E;
    }
    g_src[i] = s;
    g_dst[i] = d;
    atomicAdd(&g_deg[d], 1);
}

// ---------------- exclusive scan of deg --------------------------------------
__global__ void k_scan1(int N) {
    __shared__ int sm[256];
    int t = threadIdx.x;
    int idx = blockIdx.x * 256 + t;
    int v = (idx < N) ? g_deg[idx] : 0;
    sm[t] = v;
    __syncthreads();
#pragma unroll
    for (int off = 1; off < 256; off <<= 1) {
        int add = (t >= off) ? sm[t - off] : 0;
        __syncthreads();
        sm[t] += add;
        __syncthreads();
    }
    if (idx < N) g_ebefore[idx] = sm[t] - v;
    if (t == 255) g_blocksum[blockIdx.x] = sm[255];
}

__global__ void k_scan2(int nb) {
    __shared__ int sm[512];
    int t = threadIdx.x;
    int v = (t < nb) ? g_blocksum[t] : 0;
    sm[t] = v;
    __syncthreads();
#pragma unroll
    for (int off = 1; off < 512; off <<= 1) {
        int add = (t >= off) ? sm[t - off] : 0;
        __syncthreads();
        sm[t] += add;
        __syncthreads();
    }
    if (t < nb) g_bsumex[t] = sm[t] - v;
}

__global__ void k_scan3(int N) {
    int i = blockIdx.x * blockDim.x + threadIdx.x;
    if (i >= N) return;
    int r = g_ebefore[i] + g_bsumex[i >> 8];
    g_rowptr[i] = r;
    g_cursor[i] = r;
}

// ---------------- GEMM1: register-blocked 128x128 tile ----------------------
#define XP 136

__global__ __launch_bounds__(256, 2)
void k_gemm1(const float* __restrict__ x, const float* __restrict__ W,
             const float* __restrict__ asrc, const float* __restrict__ adst, int N) {
    __shared__ float xs[2][16 * XP];
    __shared__ float ws[2][16 * 128];
    __shared__ float sa[128], sb[128];
    __shared__ float ssb[128 * 4], sdb[128 * 4];

    int t = threadIdx.x;
    int base = blockIdx.x * 128;
    int tx = t & 15, ty = t >> 4;

    if (t < 128) { sa[t] = asrc[t]; sb[t] = adst[t]; }
    ssb[t] = 0.f; ssb[t + 256] = 0.f;
    sdb[t] = 0.f; sdb[t + 256] = 0.f;

    const float4* W4 = reinterpret_cast<const float4*>(W);

    float4 px0, px1, pw0, pw1;
    auto ldx = [&](int k0, int id) -> float4 {
        int row = id >> 2, kq = id & 3;
        int gr = base + row;
        if (gr < N) return *reinterpret_cast<const float4*>(x + (size_t)gr * 128 + k0 + kq * 4);
        return make_float4(0.f, 0.f, 0.f, 0.f);
    };

    px0 = ldx(0, t); px1 = ldx(0, t + 256);
    pw0 = W4[t]; pw1 = W4[t + 256];

    float acc[8][8];
#pragma unroll
    for (int i = 0; i < 8; i++)
#pragma unroll
        for (int j = 0; j < 8; j++) acc[i][j] = 0.f;

    auto sts = [&](int buf) {
        {
            int id = t, row = id >> 2, kq = id & 3;
            float* p = &xs[buf][(kq * 4) * XP + row];
            p[0] = px0.x; p[XP] = px0.y; p[2 * XP] = px0.z; p[3 * XP] = px0.w;
        }
        {
            int id = t + 256, row = id >> 2, kq = id & 3;
            float* p = &xs[buf][(kq * 4) * XP + row];
            p[0] = px1.x; p[XP] = px1.y; p[2 * XP] = px1.z; p[3 * XP] = px1.w;
        }
        reinterpret_cast<float4*>(ws[buf])[t] = pw0;
        reinterpret_cast<float4*>(ws[buf])[t + 256] = pw1;
    };

    sts(0);
    __syncthreads();

#pragma unroll 1
    for (int c = 0; c < 8; c++) {
        int buf = c & 1;
        if (c < 7) {
            int k0 = (c + 1) * 16;
            px0 = ldx(k0, t); px1 = ldx(k0, t + 256);
            pw0 = W4[k0 * 32 + t]; pw1 = W4[k0 * 32 + t + 256];
        }
#pragma unroll
        for (int k = 0; k < 16; k++) {
            float4 xa = *reinterpret_cast<const float4*>(&xs[buf][k * XP + ty * 4]);
            float4 xb = *reinterpret_cast<const float4*>(&xs[buf][k * XP + 64 + ty * 4]);
            float4 wa = *reinterpret_cast<const float4*>(&ws[buf][k * 128 + tx * 4]);
            float4 wb = *reinterpret_cast<const float4*>(&ws[buf][k * 128 + 64 + tx * 4]);
            float xv[8] = {xa.x, xa.y, xa.z, xa.w, xb.x, xb.y, xb.z, xb.w};
            float wv[8] = {wa.x, wa.y, wa.z, wa.w, wb.x, wb.y, wb.z, wb.w};
#pragma unroll
            for (int i = 0; i < 8; i++)
#pragma unroll
                for (int j = 0; j < 8; j++)
                    acc[i][j] += xv[i] * wv[j];
        }
        __syncthreads();
        if (c < 7) { sts(buf ^ 1); __syncthreads(); }
    }

    int hlo = tx >> 3;
    int hhi = 2 + (tx >> 3);
#pragma unroll
    for (int half = 0; half < 2; half++) {
        int rbase = half * 64 + ty * 4;
#pragma unroll
        for (int i = 0; i < 4; i++) {
            int r = rbase + i;
            int gr = base + r;
            const float* ai = acc[half * 4 + i];
            if (gr < N) {
                *reinterpret_cast<float4*>(g_h1 + (size_t)gr * 128 + tx * 4) =
                    make_float4(ai[0], ai[1], ai[2], ai[3]);
                *reinterpret_cast<float4*>(g_h1 + (size_t)gr * 128 + 64 + tx * 4) =
                    make_float4(ai[4], ai[5], ai[6], ai[7]);
            }
            float ssl = ai[0] * sa[tx * 4] + ai[1] * sa[tx * 4 + 1] + ai[2] * sa[tx * 4 + 2] + ai[3] * sa[tx * 4 + 3];
            float ssh = ai[4] * sa[64 + tx * 4] + ai[5] * sa[64 + tx * 4 + 1] + ai[6] * sa[64 + tx * 4 + 2] + ai[7] * sa[64 + tx * 4 + 3];
            float sdl = ai[0] * sb[tx * 4] + ai[1] * sb[tx * 4 + 1] + ai[2] * sb[tx * 4 + 2] + ai[3] * sb[tx * 4 + 3];
            float sdh = ai[4] * sb[64 + tx * 4] + ai[5] * sb[64 + tx * 4 + 1] + ai[6] * sb[64 + tx * 4 + 2] + ai[7] * sb[64 + tx * 4 + 3];
            atomicAdd(&ssb[r * 4 + hlo], ssl);
            atomicAdd(&ssb[r * 4 + hhi], ssh);
            atomicAdd(&sdb[r * 4 + hlo], sdl);
            atomicAdd(&sdb[r * 4 + hhi], sdh);
        }
    }
    __syncthreads();
    if (t < 128) {
        int gr = base + t;
        if (gr < N) {
            *reinterpret_cast<float4*>(g_ssrc1 + (size_t)gr * 4) =
                *reinterpret_cast<const float4*>(ssb + t * 4);
            *reinterpret_cast<float4*>(g_sdst1 + (size_t)gr * 4) =
                *reinterpret_cast<const float4*>(sdb + t * 4);
        }
    }
}

// ---------------- CSR scatter: pure permutation ------------------------------
__global__ void k_scatter(int etot) {
    int i = blockIdx.x * blockDim.x + threadIdx.x;
    if (i >= etot) return;
    int d = g_dst[i];
    int pos = atomicAdd(&g_cursor[d], 1);
    g_csr_src[pos] = g_src[i];
}

// ---------------- layer 1 aggregation: warp/dst, single pass ----------------
// out[w] = (sum_j e_j * h1[s_j]) / (sum_j e_j), e recomputed inline.
__global__ void k_agg1(int N) {
    int w = (blockIdx.x * blockDim.x + threadIdx.x) >> 5;
    if (w >= N) return;
    int lane = threadIdx.x & 31;
    int h = lane >> 3, c0 = lane * 4;
    int deg = g_deg[w], start = g_rowptr[w];
    float sd = __ldg(&g_sdst1[(size_t)w * 4 + h]);

    float4 acc = make_float4(0.f, 0.f, 0.f, 0.f);
    float den = 0.f;
    for (int j = 0; j < deg; j++) {
        int s = __ldg(&g_csr_src[start + j]);
        float ss = __ldg(&g_ssrc1[(size_t)s * 4 + h]);
        float e = __expf(lrelu(ss + sd));
        den += e;
        float4 hv = *reinterpret_cast<const float4*>(g_h1 + (size_t)s * 128 + c0);
        acc.x += e * hv.x;
        acc.y += e * hv.y;
        acc.z += e * hv.z;
        acc.w += e * hv.w;
    }
    float inv = 1.f / (den + 1e-16f);
    acc.x *= inv; acc.y *= inv; acc.z *= inv; acc.w *= inv;
    *reinterpret_cast<float4*>(g_agg1 + (size_t)w * 128 + c0) = acc;
}

// ---------------- layer 2 node kernel: elu + GEMM [N,128]@[128,32] ----------
#define XP2 264

__global__ __launch_bounds__(256, 2)
void k_layer2_node(const float* __restrict__ b1, const float* __restrict__ W2,
                   const float* __restrict__ asrc2, const float* __restrict__ adst2,
                   int N) {
    __shared__ float xs[16 * XP2];
    __shared__ float ws[128 * 32];
    __shared__ float sb1[128];
    __shared__ float sa[32], sb[32];

    int t = threadIdx.x;
    int base = blockIdx.x * 256;
    int tx = t & 7, ty = t >> 3;

    if (t < 128) sb1[t] = b1[t];
    if (t < 32) { sa[t] = asrc2[t]; sb[t] = adst2[t]; }
    for (int i = t; i < 1024; i += 256)
        reinterpret_cast<float4*>(ws)[i] = reinterpret_cast<const float4*>(W2)[i];

    float4 pf[4];
    auto ldx = [&](int k0, int id) -> float4 {
        int row = id >> 2, kq = id & 3;
        int gr = base + row;
        float4 v = make_float4(0.f, 0.f, 0.f, 0.f);
        if (gr < N) {
            v = *reinterpret_cast<const float4*>(g_agg1 + (size_t)gr * 128 + k0 + kq * 4);
            v.x += sb1[k0 + kq * 4];     v.x = v.x > 0.f ? v.x : expm1f(v.x);
            v.y += sb1[k0 + kq * 4 + 1]; v.y = v.y > 0.f ? v.y : expm1f(v.y);
            v.z += sb1[k0 + kq * 4 + 2]; v.z = v.z > 0.f ? v.z : expm1f(v.z);
            v.w += sb1[k0 + kq * 4 + 3]; v.w = v.w > 0.f ? v.w : expm1f(v.w);
        }
        return v;
    };
    __syncthreads();

#pragma unroll
    for (int j = 0; j < 4; j++) pf[j] = ldx(0, t + 256 * j);

    float acc[8][4];
#pragma unroll
    for (int i = 0; i < 8; i++)
#pragma unroll
        for (int j = 0; j < 4; j++) acc[i][j] = 0.f;

#pragma unroll 1
    for (int c = 0; c < 8; c++) {
        __syncthreads();
#pragma unroll
        for (int j = 0; j < 4; j++) {
            int id = t + 256 * j, row = id >> 2, kq = id & 3;
            float* p = &xs[(kq * 4) * XP2 + row];
            p[0] = pf[j].x; p[XP2] = pf[j].y; p[2 * XP2] = pf[j].z; p[3 * XP2] = pf[j].w;
        }
        __syncthreads();
        if (c < 7) {
            int k0 = (c + 1) * 16;
#pragma unroll
            for (int j = 0; j < 4; j++) pf[j] = ldx(k0, t + 256 * j);
        }
        int kb = c * 16;
#pragma unroll
        for (int k = 0; k < 16; k++) {
            float4 xa = *reinterpret_cast<const float4*>(&xs[k * XP2 + ty * 4]);
            float4 xb = *reinterpret_cast<const float4*>(&xs[k * XP2 + 128 + ty * 4]);
            float4 wv = *reinterpret_cast<const float4*>(&ws[(kb + k) * 32 + tx * 4]);
            float xv[8] = {xa.x, xa.y, xa.z, xa.w, xb.x, xb.y, xb.z, xb.w};
#pragma unroll
            for (int i = 0; i < 8; i++) {
                acc[i][0] += xv[i] * wv.x;
                acc[i][1] += xv[i] * wv.y;
                acc[i][2] += xv[i] * wv.z;
                acc[i][3] += xv[i] * wv.w;
            }
        }
    }

#pragma unroll
    for (int half = 0; half < 2; half++) {
#pragma unroll
        for (int i = 0; i < 4; i++) {
            int r = half * 128 + ty * 4 + i;
            int gr = base + r;
            const float* ai = acc[half * 4 + i];
            if (gr < N)
                *reinterpret_cast<float4*>(g_h2 + (size_t)gr * 32 + tx * 4) =
                    make_float4(ai[0], ai[1], ai[2], ai[3]);
            float ps = ai[0] * sa[tx * 4] + ai[1] * sa[tx * 4 + 1] + ai[2] * sa[tx * 4 + 2] + ai[3] * sa[tx * 4 + 3];
            float pd = ai[0] * sb[tx * 4] + ai[1] * sb[tx * 4 + 1] + ai[2] * sb[tx * 4 + 2] + ai[3] * sb[tx * 4 + 3];
#pragma unroll
            for (int off = 4; off; off >>= 1) {
                ps += __shfl_xor_sync(0xffffffffu, ps, off);
                pd += __shfl_xor_sync(0xffffffffu, pd, off);
            }
            if (tx == 0 && gr < N) { g_ssrc2[gr] = ps; g_sdst2[gr] = pd; }
        }
    }
}

// ---------------- layer 2 aggregation: warp/dst, single pass, fused bias ----
__global__ void k_agg2(float* __restrict__ out, const float* __restrict__ b2, int N) {
    int w = (blockIdx.x * blockDim.x + threadIdx.x) >> 5;
    if (w >= N) return;
    int lane = threadIdx.x & 31;
    int deg = g_deg[w], start = g_rowptr[w];
    float sd = __ldg(&g_sdst2[w]);

    float acc = 0.f, den = 0.f;
    for (int j = 0; j < deg; j++) {
        int s = __ldg(&g_csr_src[start + j]);
        float e = __expf(lrelu(__ldg(&g_ssrc2[s]) + sd));
        den += e;
        acc += e * __ldg(&g_h2[(size_t)s * 32 + lane]);
    }
    out[(size_t)w * 32 + lane] = acc / (den + 1e-16f) + __ldg(&b2[lane]);
}

// ---------------- launch -----------------------------------------------------
extern "C" void kernel_launch(void* const* d_in, const int* in_sizes, int n_in,
                              void* d_out, int out_size) {
    const float* x     = (const float*)d_in[0];
    const void*  ei    = d_in[1];
    const float* W1    = (const float*)d_in[2];
    const float* asrc1 = (const float*)d_in[3];
    const float* adst1 = (const float*)d_in[4];
    const float* b1    = (const float*)d_in[5];
    const float* W2    = (const float*)d_in[6];
    const float* asrc2 = (const float*)d_in[7];
    const float* adst2 = (const float*)d_in[8];
    const float* b2    = (const float*)d_in[9];
    float* out = (float*)d_out;

    int N = in_sizes[0] / 128;
    int E = in_sizes[1] / 2;
    if (N > NMAX) N = NMAX;
    if (E > EMAX) E = EMAX;
    int etot = E + N;
    int nb = (N + 255) / 256;

    k_detect_dtype<<<1, 32>>>((const int*)ei);
    k_zero_deg<<<(N + 255) / 256, 256>>>(N);
    k_build_edges<<<(etot + 255) / 256, 256>>>(ei, E, N);
    // CSR offsets
    k_scan1<<<nb, 256>>>(N);
    k_scan2<<<1, 512>>>(nb);
    k_scan3<<<(N + 255) / 256, 256>>>(N);
    k_scatter<<<(etot + 255) / 256, 256>>>(etot);
    // layer 1
    k_gemm1<<<(N + 127) / 128, 256>>>(x, W1, asrc1, adst1, N);
    k_agg1<<<(int)(((long long)N * 32 + 255) / 256), 256>>>(N);
    // layer 2
    k_layer2_node<<<(N + 255) / 256, 256>>>(b1, W2, asrc2, adst2, N);
    k_agg2<<<(int)(((long long)N * 32 + 255) / 256), 256>>>(out, b2, N);
}

// round 8
// speedup vs baseline: 4.0889x; 1.0903x over previous
#include <cuda_runtime.h>
#include <cuda_bf16.h>
#include <cstdint>
#include <cstdio>

#define NMAX 100000
#define EMAX 1600000
#define ETMAX (EMAX + NMAX)

// ---------------- scratch (device globals) ----------------------------------
__device__ __align__(256) float g_h1  [(size_t)NMAX * 128];
__device__ __align__(256) float g_agg1[(size_t)NMAX * 128];
__device__ __align__(256) float g_h2  [(size_t)NMAX * 32];
__device__ __align__(256) float g_ssrc1[NMAX * 4];
__device__ __align__(256) float g_sdst1[NMAX * 4];
__device__ __align__(256) float g_ssrc2[NMAX];
__device__ __align__(256) float g_sdst2[NMAX];
__device__ __align__(256) int   g_src[ETMAX];
__device__ __align__(256) int   g_dst[ETMAX];
__device__ __align__(256) int   g_csr_src[ETMAX];
__device__ __align__(256) int   g_deg[NMAX];
__device__ __align__(256) int   g_ebefore[NMAX];
__device__ __align__(256) int   g_rowptr[NMAX];
__device__ __align__(256) int   g_cursor[NMAX];
__device__ __align__(256) int   g_blocksum[512];
__device__ __align__(256) int   g_bsumex[512];
__device__ int g_is64;

// ---------------- helpers ---------------------------------------------------
__device__ __forceinline__ float lrelu(float v) { return v > 0.f ? v : 0.2f * v; }

// ---------------- setup ------------------------------------------------------
__global__ void k_detect_dtype(const int* __restrict__ ei32) {
    if (threadIdx.x == 0 && blockIdx.x == 0) {
        int all_zero = 1;
        for (int i = 0; i < 64; i++)
            if (ei32[2 * i + 1] != 0) { all_zero = 0; break; }
        g_is64 = all_zero;
    }
}

__global__ void k_zero_deg(int N) {
    int i = blockIdx.x * blockDim.x + threadIdx.x;
    if (i < N) g_deg[i] = 0;
}

__global__ void k_build_edges(const void* __restrict__ ei, int E, int N) {
    int i = blockIdx.x * blockDim.x + threadIdx.x;
    int etot = E + N;
    if (i >= etot) return;
    int s, d;
    if (i < E) {
        if (g_is64) {
            const long long* p = (const long long*)ei;
            s = (int)p[i];
            d = (int)p[(size_t)E + i];
        } else {
            const int* p = (const int*)ei;
            s = p[i];
            d = p[E + i];
        }
        s = min(max(s, 0), N - 1);
        d = min(max(d, 0), N - 1);
    } else {
        s = i - E;
        d = i - E;
    }
    g_src[i] = s;
    g_dst[i] = d;
    atomicAdd(&g_deg[d], 1);
}

// ---------------- exclusive scan of deg --------------------------------------
__global__ void k_scan1(int N) {
    __shared__ int sm[256];
    int t = threadIdx.x;
    int idx = blockIdx.x * 256 + t;
    int v = (idx < N) ? g_deg[idx] : 0;
    sm[t] = v;
    __syncthreads();
#pragma unroll
    for (int off = 1; off < 256; off <<= 1) {
        int add = (t >= off) ? sm[t - off] : 0;
        __syncthreads();
        sm[t] += add;
        __syncthreads();
    }
    if (idx < N) g_ebefore[idx] = sm[t] - v;
    if (t == 255) g_blocksum[blockIdx.x] = sm[255];
}

__global__ void k_scan2(int nb) {
    __shared__ int sm[512];
    int t = threadIdx.x;
    int v = (t < nb) ? g_blocksum[t] : 0;
    sm[t] = v;
    __syncthreads();
#pragma unroll
    for (int off = 1; off < 512; off <<= 1) {
        int add = (t >= off) ? sm[t - off] : 0;
        __syncthreads();
        sm[t] += add;
        __syncthreads();
    }
    if (t < nb) g_bsumex[t] = sm[t] - v;
}

__global__ void k_scan3(int N) {
    int i = blockIdx.x * blockDim.x + threadIdx.x;
    if (i >= N) return;
    int r = g_ebefore[i] + g_bsumex[i >> 8];
    g_rowptr[i] = r;
    g_cursor[i] = r;
}

// ---------------- GEMM1: register-blocked 128x128 tile ----------------------
#define XP 136

__global__ __launch_bounds__(256, 2)
void k_gemm1(const float* __restrict__ x, const float* __restrict__ W,
             const float* __restrict__ asrc, const float* __restrict__ adst, int N) {
    __shared__ float xs[2][16 * XP];
    __shared__ float ws[2][16 * 128];
    __shared__ float sa[128], sb[128];
    __shared__ float ssb[128 * 4], sdb[128 * 4];

    int t = threadIdx.x;
    int base = blockIdx.x * 128;
    int tx = t & 15, ty = t >> 4;

    if (t < 128) { sa[t] = asrc[t]; sb[t] = adst[t]; }
    ssb[t] = 0.f; ssb[t + 256] = 0.f;
    sdb[t] = 0.f; sdb[t + 256] = 0.f;

    const float4* W4 = reinterpret_cast<const float4*>(W);

    float4 px0, px1, pw0, pw1;
    auto ldx = [&](int k0, int id) -> float4 {
        int row = id >> 2, kq = id & 3;
        int gr = base + row;
        if (gr < N) return *reinterpret_cast<const float4*>(x + (size_t)gr * 128 + k0 + kq * 4);
        return make_float4(0.f, 0.f, 0.f, 0.f);
    };

    px0 = ldx(0, t); px1 = ldx(0, t + 256);
    pw0 = W4[t]; pw1 = W4[t + 256];

    float acc[8][8];
#pragma unroll
    for (int i = 0; i < 8; i++)
#pragma unroll
        for (int j = 0; j < 8; j++) acc[i][j] = 0.f;

    auto sts = [&](int buf) {
        {
            int id = t, row = id >> 2, kq = id & 3;
            float* p = &xs[buf][(kq * 4) * XP + row];
            p[0] = px0.x; p[XP] = px0.y; p[2 * XP] = px0.z; p[3 * XP] = px0.w;
        }
        {
            int id = t + 256, row = id >> 2, kq = id & 3;
            float* p = &xs[buf][(kq * 4) * XP + row];
            p[0] = px1.x; p[XP] = px1.y; p[2 * XP] = px1.z; p[3 * XP] = px1.w;
        }
        reinterpret_cast<float4*>(ws[buf])[t] = pw0;
        reinterpret_cast<float4*>(ws[buf])[t + 256] = pw1;
    };

    sts(0);
    __syncthreads();

#pragma unroll 1
    for (int c = 0; c < 8; c++) {
        int buf = c & 1;
        if (c < 7) {
            int k0 = (c + 1) * 16;
            px0 = ldx(k0, t); px1 = ldx(k0, t + 256);
            pw0 = W4[k0 * 32 + t]; pw1 = W4[k0 * 32 + t + 256];
        }
#pragma unroll
        for (int k = 0; k < 16; k++) {
            float4 xa = *reinterpret_cast<const float4*>(&xs[buf][k * XP + ty * 4]);
            float4 xb = *reinterpret_cast<const float4*>(&xs[buf][k * XP + 64 + ty * 4]);
            float4 wa = *reinterpret_cast<const float4*>(&ws[buf][k * 128 + tx * 4]);
            float4 wb = *reinterpret_cast<const float4*>(&ws[buf][k * 128 + 64 + tx * 4]);
            float xv[8] = {xa.x, xa.y, xa.z, xa.w, xb.x, xb.y, xb.z, xb.w};
            float wv[8] = {wa.x, wa.y, wa.z, wa.w, wb.x, wb.y, wb.z, wb.w};
#pragma unroll
            for (int i = 0; i < 8; i++)
#pragma unroll
                for (int j = 0; j < 8; j++)
                    acc[i][j] += xv[i] * wv[j];
        }
        __syncthreads();
        if (c < 7) { sts(buf ^ 1); __syncthreads(); }
    }

    int hlo = tx >> 3;
    int hhi = 2 + (tx >> 3);
#pragma unroll
    for (int half = 0; half < 2; half++) {
        int rbase = half * 64 + ty * 4;
#pragma unroll
        for (int i = 0; i < 4; i++) {
            int r = rbase + i;
            int gr = base + r;
            const float* ai = acc[half * 4 + i];
            if (gr < N) {
                *reinterpret_cast<float4*>(g_h1 + (size_t)gr * 128 + tx * 4) =
                    make_float4(ai[0], ai[1], ai[2], ai[3]);
                *reinterpret_cast<float4*>(g_h1 + (size_t)gr * 128 + 64 + tx * 4) =
                    make_float4(ai[4], ai[5], ai[6], ai[7]);
            }
            float ssl = ai[0] * sa[tx * 4] + ai[1] * sa[tx * 4 + 1] + ai[2] * sa[tx * 4 + 2] + ai[3] * sa[tx * 4 + 3];
            float ssh = ai[4] * sa[64 + tx * 4] + ai[5] * sa[64 + tx * 4 + 1] + ai[6] * sa[64 + tx * 4 + 2] + ai[7] * sa[64 + tx * 4 + 3];
            float sdl = ai[0] * sb[tx * 4] + ai[1] * sb[tx * 4 + 1] + ai[2] * sb[tx * 4 + 2] + ai[3] * sb[tx * 4 + 3];
            float sdh = ai[4] * sb[64 + tx * 4] + ai[5] * sb[64 + tx * 4 + 1] + ai[6] * sb[64 + tx * 4 + 2] + ai[7] * sb[64 + tx * 4 + 3];
            atomicAdd(&ssb[r * 4 + hlo], ssl);
            atomicAdd(&ssb[r * 4 + hhi], ssh);
            atomicAdd(&sdb[r * 4 + hlo], sdl);
            atomicAdd(&sdb[r * 4 + hhi], sdh);
        }
    }
    __syncthreads();
    if (t < 128) {
        int gr = base + t;
        if (gr < N) {
            *reinterpret_cast<float4*>(g_ssrc1 + (size_t)gr * 4) =
                *reinterpret_cast<const float4*>(ssb + t * 4);
            *reinterpret_cast<float4*>(g_sdst1 + (size_t)gr * 4) =
                *reinterpret_cast<const float4*>(sdb + t * 4);
        }
    }
}

// ---------------- CSR scatter: pure permutation ------------------------------
__global__ void k_scatter(int etot) {
    int i = blockIdx.x * blockDim.x + threadIdx.x;
    if (i >= etot) return;
    int d = g_dst[i];
    int pos = atomicAdd(&g_cursor[d], 1);
    g_csr_src[pos] = g_src[i];
}

// ---------------- layer 1 aggregation: warp/dst, single pass ----------------
__global__ void k_agg1(int N) {
    int w = (blockIdx.x * blockDim.x + threadIdx.x) >> 5;
    if (w >= N) return;
    int lane = threadIdx.x & 31;
    int h = lane >> 3, c0 = lane * 4;
    int deg = g_deg[w], start = g_rowptr[w];
    float sd = __ldg(&g_sdst1[(size_t)w * 4 + h]);

    float4 acc = make_float4(0.f, 0.f, 0.f, 0.f);
    float den = 0.f;

    int j = 0;
    // unrolled x2 with index prefetch for MLP
    for (; j + 2 <= deg; j += 2) {
        int s0 = __ldg(&g_csr_src[start + j]);
        int s1 = __ldg(&g_csr_src[start + j + 1]);
        float ss0 = __ldg(&g_ssrc1[(size_t)s0 * 4 + h]);
        float ss1 = __ldg(&g_ssrc1[(size_t)s1 * 4 + h]);
        float4 hv0 = *reinterpret_cast<const float4*>(g_h1 + (size_t)s0 * 128 + c0);
        float4 hv1 = *reinterpret_cast<const float4*>(g_h1 + (size_t)s1 * 128 + c0);
        float e0 = __expf(lrelu(ss0 + sd));
        float e1 = __expf(lrelu(ss1 + sd));
        den += e0 + e1;
        acc.x += e0 * hv0.x + e1 * hv1.x;
        acc.y += e0 * hv0.y + e1 * hv1.y;
        acc.z += e0 * hv0.z + e1 * hv1.z;
        acc.w += e0 * hv0.w + e1 * hv1.w;
    }
    for (; j < deg; j++) {
        int s = __ldg(&g_csr_src[start + j]);
        float ss = __ldg(&g_ssrc1[(size_t)s * 4 + h]);
        float e = __expf(lrelu(ss + sd));
        den += e;
        float4 hv = *reinterpret_cast<const float4*>(g_h1 + (size_t)s * 128 + c0);
        acc.x += e * hv.x;
        acc.y += e * hv.y;
        acc.z += e * hv.z;
        acc.w += e * hv.w;
    }
    float inv = 1.f / (den + 1e-16f);
    acc.x *= inv; acc.y *= inv; acc.z *= inv; acc.w *= inv;
    *reinterpret_cast<float4*>(g_agg1 + (size_t)w * 128 + c0) = acc;
}

// ---------------- layer 2 node kernel: elu + GEMM [N,128]@[128,32] ----------
#define XP2 264

__global__ __launch_bounds__(256, 2)
void k_layer2_node(const float* __restrict__ b1, const float* __restrict__ W2,
                   const float* __restrict__ asrc2, const float* __restrict__ adst2,
                   int N) {
    __shared__ float xs[16 * XP2];
    __shared__ float ws[128 * 32];
    __shared__ float sb1[128];
    __shared__ float sa[32], sb[32];

    int t = threadIdx.x;
    int base = blockIdx.x * 256;
    int tx = t & 7, ty = t >> 3;

    if (t < 128) sb1[t] = b1[t];
    if (t < 32) { sa[t] = asrc2[t]; sb[t] = adst2[t]; }
    for (int i = t; i < 1024; i += 256)
        reinterpret_cast<float4*>(ws)[i] = reinterpret_cast<const float4*>(W2)[i];

    float4 pf[4];
    auto ldx = [&](int k0, int id) -> float4 {
        int row = id >> 2, kq = id & 3;
        int gr = base + row;
        float4 v = make_float4(0.f, 0.f, 0.f, 0.f);
        if (gr < N) {
            v = *reinterpret_cast<const float4*>(g_agg1 + (size_t)gr * 128 + k0 + kq * 4);
            v.x += sb1[k0 + kq * 4];     v.x = v.x > 0.f ? v.x : expm1f(v.x);
            v.y += sb1[k0 + kq * 4 + 1]; v.y = v.y > 0.f ? v.y : expm1f(v.y);
            v.z += sb1[k0 + kq * 4 + 2]; v.z = v.z > 0.f ? v.z : expm1f(v.z);
            v.w += sb1[k0 + kq * 4 + 3]; v.w = v.w > 0.f ? v.w : expm1f(v.w);
        }
        return v;
    };
    __syncthreads();

#pragma unroll
    for (int j = 0; j < 4; j++) pf[j] = ldx(0, t + 256 * j);

    float acc[8][4];
#pragma unroll
    for (int i = 0; i < 8; i++)
#pragma unroll
        for (int j = 0; j < 4; j++) acc[i][j] = 0.f;

#pragma unroll 1
    for (int c = 0; c < 8; c++) {
        __syncthreads();
#pragma unroll
        for (int j = 0; j < 4; j++) {
            int id = t + 256 * j, row = id >> 2, kq = id & 3;
            float* p = &xs[(kq * 4) * XP2 + row];
            p[0] = pf[j].x; p[XP2] = pf[j].y; p[2 * XP2] = pf[j].z; p[3 * XP2] = pf[j].w;
        }
        __syncthreads();
        if (c < 7) {
            int k0 = (c + 1) * 16;
#pragma unroll
            for (int j = 0; j < 4; j++) pf[j] = ldx(k0, t + 256 * j);
        }
        int kb = c * 16;
#pragma unroll
        for (int k = 0; k < 16; k++) {
            float4 xa = *reinterpret_cast<const float4*>(&xs[k * XP2 + ty * 4]);
            float4 xb = *reinterpret_cast<const float4*>(&xs[k * XP2 + 128 + ty * 4]);
            float4 wv = *reinterpret_cast<const float4*>(&ws[(kb + k) * 32 + tx * 4]);
            float xv[8] = {xa.x, xa.y, xa.z, xa.w, xb.x, xb.y, xb.z, xb.w};
#pragma unroll
            for (int i = 0; i < 8; i++) {
                acc[i][0] += xv[i] * wv.x;
                acc[i][1] += xv[i] * wv.y;
                acc[i][2] += xv[i] * wv.z;
                acc[i][3] += xv[i] * wv.w;
            }
        }
    }

#pragma unroll
    for (int half = 0; half < 2; half++) {
#pragma unroll
        for (int i = 0; i < 4; i++) {
            int r = half * 128 + ty * 4 + i;
            int gr = base + r;
            const float* ai = acc[half * 4 + i];
            if (gr < N)
                *reinterpret_cast<float4*>(g_h2 + (size_t)gr * 32 + tx * 4) =
                    make_float4(ai[0], ai[1], ai[2], ai[3]);
            float ps = ai[0] * sa[tx * 4] + ai[1] * sa[tx * 4 + 1] + ai[2] * sa[tx * 4 + 2] + ai[3] * sa[tx * 4 + 3];
            float pd = ai[0] * sb[tx * 4] + ai[1] * sb[tx * 4 + 1] + ai[2] * sb[tx * 4 + 2] + ai[3] * sb[tx * 4 + 3];
#pragma unroll
            for (int off = 4; off; off >>= 1) {
                ps += __shfl_xor_sync(0xffffffffu, ps, off);
                pd += __shfl_xor_sync(0xffffffffu, pd, off);
            }
            if (tx == 0 && gr < N) { g_ssrc2[gr] = ps; g_sdst2[gr] = pd; }
        }
    }
}

// ---------------- layer 2 aggregation: warp/dst, single pass, fused bias ----
__global__ void k_agg2(float* __restrict__ out, const float* __restrict__ b2, int N) {
    int w = (blockIdx.x * blockDim.x + threadIdx.x) >> 5;
    if (w >= N) return;
    int lane = threadIdx.x & 31;
    int deg = g_deg[w], start = g_rowptr[w];
    float sd = __ldg(&g_sdst2[w]);

    float acc = 0.f, den = 0.f;
    int j = 0;
    for (; j + 2 <= deg; j += 2) {
        int s0 = __ldg(&g_csr_src[start + j]);
        int s1 = __ldg(&g_csr_src[start + j + 1]);
        float e0 = __expf(lrelu(__ldg(&g_ssrc2[s0]) + sd));
        float e1 = __expf(lrelu(__ldg(&g_ssrc2[s1]) + sd));
        float v0 = __ldg(&g_h2[(size_t)s0 * 32 + lane]);
        float v1 = __ldg(&g_h2[(size_t)s1 * 32 + lane]);
        den += e0 + e1;
        acc += e0 * v0 + e1 * v1;
    }
    for (; j < deg; j++) {
        int s = __ldg(&g_csr_src[start + j]);
        float e = __expf(lrelu(__ldg(&g_ssrc2[s]) + sd));
        den += e;
        acc += e * __ldg(&g_h2[(size_t)s * 32 + lane]);
    }
    out[(size_t)w * 32 + lane] = acc / (den + 1e-16f) + __ldg(&b2[lane]);
}

// ---------------- launch -----------------------------------------------------
static cudaStream_t g_s2 = nullptr;
static cudaEvent_t  g_evFork = nullptr, g_evJoin = nullptr;

extern "C" void kernel_launch(void* const* d_in, const int* in_sizes, int n_in,
                              void* d_out, int out_size) {
    const float* x     = (const float*)d_in[0];
    const void*  ei    = d_in[1];
    const float* W1    = (const float*)d_in[2];
    const float* asrc1 = (const float*)d_in[3];
    const float* adst1 = (const float*)d_in[4];
    const float* b1    = (const float*)d_in[5];
    const float* W2    = (const float*)d_in[6];
    const float* asrc2 = (const float*)d_in[7];
    const float* adst2 = (const float*)d_in[8];
    const float* b2    = (const float*)d_in[9];
    float* out = (float*)d_out;

    int N = in_sizes[0] / 128;
    int E = in_sizes[1] / 2;
    if (N > NMAX) N = NMAX;
    if (E > EMAX) E = EMAX;
    int etot = E + N;
    int nb = (N + 255) / 256;

    if (g_s2 == nullptr) {   // one-time resource creation (first call is outside capture)
        cudaStreamCreateWithFlags(&g_s2, cudaStreamNonBlocking);
        cudaEventCreateWithFlags(&g_evFork, cudaEventDisableTiming);
        cudaEventCreateWithFlags(&g_evJoin, cudaEventDisableTiming);
    }

    // fork: CSR-build chain on s2, concurrent with gemm1 on main stream
    cudaEventRecord(g_evFork, 0);
    cudaStreamWaitEvent(g_s2, g_evFork, 0);

    k_detect_dtype<<<1, 32, 0, g_s2>>>((const int*)ei);
    k_zero_deg<<<(N + 255) / 256, 256, 0, g_s2>>>(N);
    k_build_edges<<<(etot + 255) / 256, 256, 0, g_s2>>>(ei, E, N);
    k_scan1<<<nb, 256, 0, g_s2>>>(N);
    k_scan2<<<1, 512, 0, g_s2>>>(nb);
    k_scan3<<<(N + 255) / 256, 256, 0, g_s2>>>(N);
    k_scatter<<<(etot + 255) / 256, 256, 0, g_s2>>>(etot);
    cudaEventRecord(g_evJoin, g_s2);

    // main stream: gemm1 runs concurrently with the chain above
    k_gemm1<<<(N + 127) / 128, 256>>>(x, W1, asrc1, adst1, N);

    // join, then the dependent pipeline
    cudaStreamWaitEvent(0, g_evJoin, 0);
    k_agg1<<<(int)(((long long)N * 32 + 255) / 256), 256>>>(N);
    k_layer2_node<<<(N + 255) / 256, 256>>>(b1, W2, asrc2, adst2, N);
    k_agg2<<<(int)(((long long)N * 32 + 255) / 256), 256>>>(out, b2, N);
}